// round 10
// baseline (speedup 1.0000x reference)
#include <cuda_runtime.h>
#include <cuda_bf16.h>

#define FULL_MASK 0xFFFFFFFFu

// Persistent grid-stride warps (2368 blocks x 128 thr = full 2048-thr/SM
// residency on 148 SMs), 4 lanes/row, 8 rows per warp-region, ~13 regions
// per warp. Decide scheme = R3/R9 (early-exit chunks of 4 over cols 1..63).
// Cross-iteration pipeline: the NEXT region's score + chunk-0 nidx loads are
// issued before the CURRENT region's write phase, hiding the ~600-cycle
// decide-chain head latency behind the 16 store instructions.
__global__ void __launch_bounds__(128)
dgb_kernel(const float4* __restrict__ dist4,
           const int*    __restrict__ nidx,
           const float*  __restrict__ score,
           float4* __restrict__ dist_out4,
           float4* __restrict__ nidx_out4,
           long long V)
{
    const long long total_regions = (V + 7) >> 3;
    long long nwarps = ((long long)gridDim.x * blockDim.x) >> 5;
    long long region = ((long long)blockIdx.x * blockDim.x + threadIdx.x) >> 5;
    int lane = threadIdx.x & 31;
    int g = lane >> 2;                  // row group within warp: 0..7
    int l = lane & 3;                   // lane within group: 0..3
    unsigned grpmask = 0xFu << (g << 2);

    if (region >= total_regions) return;

    // ---- preload for first region ----
    long long row = region * 8 + g;
    bool valid = row < V;
    float sv = valid ? __ldg(score + row) : 3.0f;     // >1 => never beaten
    const int* nrow = nidx + (valid ? row : 0) * 64;
    int ni0 = __ldg(nrow + 1 + l);                    // chunk 0: cols 1..4

    const int4* nidx4 = (const int4*)nidx;

    while (true) {
        // ---- decide current region ----
        bool beat0 = (ni0 >= 0) && (__ldg(score + ni0) > sv);  // strict
        bool cond = __any_sync(grpmask, beat0);
        if (!cond) {
            #pragma unroll 1
            for (int j = 1; j < 16; ++j) {
                int col = (j << 2) + 1 + l;           // 5..64 (64 guarded)
                bool beat = false;
                if (col < 64) {
                    int ni = __ldg(nrow + col);
                    if (ni >= 0)
                        beat = __ldg(score + ni) > sv;
                }
                if (__any_sync(grpmask, beat)) { cond = true; break; }
            }
        }
        unsigned bal = __ballot_sync(FULL_MASK, cond);

        // ---- issue next region's head loads BEFORE the write phase ----
        long long next = region + nwarps;
        bool have_next = next < total_regions;
        float sv_n = 3.0f;
        int ni0_n = -1;
        const int* nrow_n = nidx;
        if (have_next) {
            long long rown = next * 8 + g;
            bool vn = rown < V;
            sv_n = vn ? __ldg(score + rown) : 3.0f;
            nrow_n = nidx + (vn ? rown : 0) * 64;
            ni0_n = __ldg(nrow_n + 1 + l);
        }

        // ---- write phase: contiguous streaming over region's 8 rows ----
        long long warp_row0 = region * 8;
        long long gbase = warp_row0 * 16;   // float4 index of region start
        #pragma unroll
        for (int t = 0; t < 4; ++t) {
            int vec = t * 32 + lane;        // 0..127 within region
            int row_local = vec >> 4;       // 0..7
            int within = vec & 15;          // float4 within row
            long long rr = warp_row0 + row_local;
            if (rr >= V) continue;
            long long idx = gbase + vec;

            bool c = (bal >> (row_local << 2)) & 1u;

            float4 dv, nv;
            if (c) {
                dv = make_float4(0.f, 0.f, 0.f, 0.f);
                nv = make_float4(-1.f, -1.f, -1.f, -1.f);
                if (within == 0) nv.x = (float)rr;
            } else {
                dv = __ldg(dist4 + idx);
                int4 niv = __ldg(nidx4 + idx);
                nv = make_float4((float)niv.x, (float)niv.y,
                                 (float)niv.z, (float)niv.w);
            }
            dist_out4[idx] = dv;
            nidx_out4[idx] = nv;
        }

        if (!have_next) break;
        region = next;
        sv = sv_n;
        ni0 = ni0_n;
        nrow = nrow_n;
    }
}

extern "C" void kernel_launch(void* const* d_in, const int* in_sizes, int n_in,
                              void* d_out, int out_size)
{
    const float* dist  = (const float*)d_in[0];   // [V, 64] f32
    const int*   nidx  = (const int*)d_in[1];     // [V, 64] i32
    const float* score = (const float*)d_in[2];   // [V, 1]  f32

    long long V = in_sizes[2];                    // score element count == V

    float* out      = (float*)d_out;
    float* dist_out = out;                        // first V*64 floats
    float* nidx_out = out + V * 64;               // second V*64 (ints as f32)

    int threads = 128;
    // Full residency: 16 blocks/SM x 148 SMs (128 thr, 31 regs -> 2048 thr/SM)
    long long needed = ((V * 4) + threads - 1) / threads;
    long long blocks = 148LL * 16;
    if (blocks > needed) blocks = needed;

    dgb_kernel<<<(unsigned int)blocks, threads>>>(
        (const float4*)dist, nidx, score,
        (float4*)dist_out, (float4*)nidx_out, V);
}

// round 11
// speedup vs baseline: 1.2353x; 1.2353x over previous
#include <cuda_runtime.h>
#include <cuda_bf16.h>

#define FULL_MASK 0xFFFFFFFFu

// R9 scheme (best known: 106.7us) with 64-thread blocks.
// Evidence chain: 256->128 thr raised achieved occupancy 74.6->78.5% and cut
// 2.3us (block retirement waits on the slowest decide chain; smaller blocks
// shrink that granularity). 64-thr blocks (2 warps) quarter it again while
// keeping full 2048-thr/SM theoretical residency (32 blocks/SM cap).
// 4 lanes per row, 8 rows per warp. Early-exit scan over columns 1..63
// (column 0 = self, never gathered) in chunks of 4, per-group exit.
// Write phase streams the warp's 8 contiguous rows coalesced (512B/instr).
__global__ void __launch_bounds__(64)
dgb_kernel(const float4* __restrict__ dist4,
           const int*    __restrict__ nidx,
           const float*  __restrict__ score,
           float4* __restrict__ dist_out4,
           float4* __restrict__ nidx_out4,
           long long V)
{
    long long warp_id = ((long long)blockIdx.x * blockDim.x + threadIdx.x) >> 5;
    int lane = threadIdx.x & 31;
    int g = lane >> 2;                 // row group within warp: 0..7
    int l = lane & 3;                  // lane within group: 0..3
    unsigned grpmask = 0xFu << (g << 2);

    long long row = warp_id * 8 + g;
    bool valid = row < V;
    long long srow = valid ? row : 0;

    float sv = valid ? __ldg(score + row) : 3.0f;   // >1 => never beaten
    const int* nrow = nidx + srow * 64;

    // ---- early-exit decide: chunks of 4 over columns 1..63 ----
    bool cond = false;                 // true => some neighbour beats sv
    #pragma unroll 1
    for (int j = 0; j < 16; ++j) {
        int col = (j << 2) + 1 + l;    // 1..64 (64 guarded off)
        bool beat = false;
        if (col < 64) {
            int ni = __ldg(nrow + col);
            if (ni >= 0)
                beat = __ldg(score + ni) > sv;   // strict: matches diff < 0
        }
        if (__any_sync(grpmask, beat)) { cond = true; break; }
    }

    // Publish cond bits for all 8 rows of this warp (bit at lane g*4).
    unsigned bal = __ballot_sync(FULL_MASK, cond);

    // ---- write phase: contiguous streaming over the warp's 8 rows ----
    long long warp_row0 = warp_id * 8;
    long long gbase = warp_row0 * 16;  // float4 index of region start
    const int4* nidx4 = (const int4*)nidx;

    #pragma unroll
    for (int t = 0; t < 4; ++t) {
        int vec = t * 32 + lane;       // 0..127 within warp region
        int row_local = vec >> 4;      // 0..7
        int within = vec & 15;         // float4 within row
        long long rr = warp_row0 + row_local;
        if (rr >= V) continue;
        long long idx = gbase + vec;

        bool c = (bal >> (row_local << 2)) & 1u;

        float4 dv, nv;
        if (c) {
            dv = make_float4(0.f, 0.f, 0.f, 0.f);
            nv = make_float4(-1.f, -1.f, -1.f, -1.f);
            if (within == 0) nv.x = (float)rr;
        } else {
            dv = __ldg(dist4 + idx);
            int4 niv = __ldg(nidx4 + idx);
            nv = make_float4((float)niv.x, (float)niv.y,
                             (float)niv.z, (float)niv.w);
        }
        dist_out4[idx] = dv;
        nidx_out4[idx] = nv;
    }
}

extern "C" void kernel_launch(void* const* d_in, const int* in_sizes, int n_in,
                              void* d_out, int out_size)
{
    const float* dist  = (const float*)d_in[0];   // [V, 64] f32
    const int*   nidx  = (const int*)d_in[1];     // [V, 64] i32
    const float* score = (const float*)d_in[2];   // [V, 1]  f32

    long long V = in_sizes[2];                    // score element count == V

    float* out      = (float*)d_out;
    float* dist_out = out;                        // first V*64 floats
    float* nidx_out = out + V * 64;               // second V*64 (ints as f32)

    // 4 lanes per row -> V*4 threads
    long long total_threads = V * 4;
    int threads = 64;
    long long blocks = (total_threads + threads - 1) / threads;

    dgb_kernel<<<(unsigned int)blocks, threads>>>(
        (const float4*)dist, nidx, score,
        (float4*)dist_out, (float4*)nidx_out, V);
}

// round 12
// speedup vs baseline: 1.2405x; 1.0042x over previous
#include <cuda_runtime.h>
#include <cuda_bf16.h>

#define FULL_MASK 0xFFFFFFFFu

// R9 base (best: 106.7us): 4 lanes/row, 8 rows/warp, 128-thr blocks.
// Chunk 0 (cols 1..4) identical to R9 — decides 80% of rows with 4 gathers.
// Straggler loop: TWO 4-col chunks per ballot (8 concurrent gathers, one
// __any_sync) -> straggler round trips halve; extra speculative gathers only
// on the rare (~20% of rows) straggler path. Pass-through loads use __ldcs
// (use-once; don't evict hot decide lines from L1).
__global__ void __launch_bounds__(128)
dgb_kernel(const float4* __restrict__ dist4,
           const int*    __restrict__ nidx,
           const float*  __restrict__ score,
           float4* __restrict__ dist_out4,
           float4* __restrict__ nidx_out4,
           long long V)
{
    long long warp_id = ((long long)blockIdx.x * blockDim.x + threadIdx.x) >> 5;
    int lane = threadIdx.x & 31;
    int g = lane >> 2;                 // row group within warp: 0..7
    int l = lane & 3;                  // lane within group: 0..3
    unsigned grpmask = 0xFu << (g << 2);

    long long row = warp_id * 8 + g;
    bool valid = row < V;
    long long srow = valid ? row : 0;

    float sv = valid ? __ldg(score + row) : 3.0f;   // >1 => never beaten
    const int* nrow = nidx + srow * 64;

    // ---- chunk 0: cols 1..4 (common path, identical to R9) ----
    bool cond;
    {
        int ni = __ldg(nrow + 1 + l);
        bool beat = (ni >= 0) && (__ldg(score + ni) > sv);  // strict
        cond = __any_sync(grpmask, beat);
    }

    // ---- straggler loop: two 4-col chunks per ballot ----
    if (!cond) {
        #pragma unroll 1
        for (int j = 1; j < 16; j += 2) {
            int colA = (j << 2) + 1 + l;        // 5..64   (64 guarded)
            int colB = colA + 4;                // 9..68   (>=64 guarded)
            int niA = (colA < 64) ? __ldg(nrow + colA) : -1;
            int niB = (colB < 64) ? __ldg(nrow + colB) : -1;
            float vA = __ldg(score + max(niA, 0));
            float vB = __ldg(score + max(niB, 0));
            bool beat = ((niA >= 0) & (vA > sv)) |
                        ((niB >= 0) & (vB > sv));
            if (__any_sync(grpmask, beat)) { cond = true; break; }
        }
    }

    // Publish cond bits for all 8 rows of this warp (bit at lane g*4).
    unsigned bal = __ballot_sync(FULL_MASK, cond);

    // ---- write phase: contiguous streaming over the warp's 8 rows ----
    long long warp_row0 = warp_id * 8;
    long long gbase = warp_row0 * 16;  // float4 index of region start
    const int4* nidx4 = (const int4*)nidx;

    #pragma unroll
    for (int t = 0; t < 4; ++t) {
        int vec = t * 32 + lane;       // 0..127 within warp region
        int row_local = vec >> 4;      // 0..7
        int within = vec & 15;         // float4 within row
        long long rr = warp_row0 + row_local;
        if (rr >= V) continue;
        long long idx = gbase + vec;

        bool c = (bal >> (row_local << 2)) & 1u;

        float4 dv, nv;
        if (c) {
            dv = make_float4(0.f, 0.f, 0.f, 0.f);
            nv = make_float4(-1.f, -1.f, -1.f, -1.f);
            if (within == 0) nv.x = (float)rr;
        } else {
            dv = __ldcs(dist4 + idx);
            int4 niv = __ldcs(nidx4 + idx);
            nv = make_float4((float)niv.x, (float)niv.y,
                             (float)niv.z, (float)niv.w);
        }
        dist_out4[idx] = dv;
        nidx_out4[idx] = nv;
    }
}

extern "C" void kernel_launch(void* const* d_in, const int* in_sizes, int n_in,
                              void* d_out, int out_size)
{
    const float* dist  = (const float*)d_in[0];   // [V, 64] f32
    const int*   nidx  = (const int*)d_in[1];     // [V, 64] i32
    const float* score = (const float*)d_in[2];   // [V, 1]  f32

    long long V = in_sizes[2];                    // score element count == V

    float* out      = (float*)d_out;
    float* dist_out = out;                        // first V*64 floats
    float* nidx_out = out + V * 64;               // second V*64 (ints as f32)

    // 4 lanes per row -> V*4 threads
    long long total_threads = V * 4;
    int threads = 128;
    long long blocks = (total_threads + threads - 1) / threads;

    dgb_kernel<<<(unsigned int)blocks, threads>>>(
        (const float4*)dist, nidx, score,
        (float4*)dist_out, (float4*)nidx_out, V);
}